// round 12
// baseline (speedup 1.0000x reference)
#include <cuda_runtime.h>
#include <cuda_bf16.h>
#include <cstdint>

// Problem constants
#define BB 4
#define TT 4096
#define CC 1024
#define HH 128

// ---------------------------------------------------------------------------
// Device scratch (no allocations allowed). Q/K/V live ONLY as split bf16.
// ---------------------------------------------------------------------------
__device__ __nv_bfloat16 g_Qhi[BB * TT * HH];
__device__ __nv_bfloat16 g_Qlo[BB * TT * HH];
__device__ __nv_bfloat16 g_Khi[BB * TT * HH];
__device__ __nv_bfloat16 g_Klo[BB * TT * HH];
__device__ __nv_bfloat16 g_Vhi[BB * TT * HH];
__device__ __nv_bfloat16 g_Vlo[BB * TT * HH];
__device__ __nv_bfloat16 g_Bhi[3 * HH * CC];        // W^T split-hi [3][128][1024]
__device__ __nv_bfloat16 g_Blo[3 * HH * CC];        // W^T split-lo

// ---------------------------------------------------------------------------
// Helpers (baseline sm_100 PTX: ldmatrix + mma.sync + cp.async)
// ---------------------------------------------------------------------------
__device__ __forceinline__ uint32_t smem_u32(const void* p) {
    uint32_t a;
    asm("{ .reg .u64 t; cvta.to.shared.u64 t, %1; cvt.u32.u64 %0, t; }"
        : "=r"(a) : "l"(p));
    return a;
}

#define LDMX4(r, addr) \
    asm volatile("ldmatrix.sync.aligned.m8n8.x4.shared.b16 {%0,%1,%2,%3}, [%4];" \
        : "=r"((r)[0]), "=r"((r)[1]), "=r"((r)[2]), "=r"((r)[3]) : "r"(addr))

#define LDMX4T(r, addr) \
    asm volatile("ldmatrix.sync.aligned.m8n8.x4.trans.shared.b16 {%0,%1,%2,%3}, [%4];" \
        : "=r"((r)[0]), "=r"((r)[1]), "=r"((r)[2]), "=r"((r)[3]) : "r"(addr))

#define MMA_BF16(c, a, b0, b1) \
    asm volatile("mma.sync.aligned.m16n8k16.row.col.f32.bf16.bf16.f32 " \
        "{%0,%1,%2,%3}, {%4,%5,%6,%7}, {%8,%9}, {%0,%1,%2,%3};" \
        : "+f"((c)[0]), "+f"((c)[1]), "+f"((c)[2]), "+f"((c)[3]) \
        : "r"((a)[0]), "r"((a)[1]), "r"((a)[2]), "r"((a)[3]), "r"(b0), "r"(b1))

#define CP_ASYNC16(saddr, gptr) \
    asm volatile("cp.async.cg.shared.global [%0], [%1], 16;" \
        :: "r"(saddr), "l"(gptr) : "memory")
#define CP_COMMIT() asm volatile("cp.async.commit_group;" ::: "memory")
#define CP_WAIT0()  asm volatile("cp.async.wait_group 0;" ::: "memory")

__device__ __forceinline__ uint32_t pack_bf2(__nv_bfloat16 a, __nv_bfloat16 b) {
    return (uint32_t)__bfloat16_as_ushort(a) |
           ((uint32_t)__bfloat16_as_ushort(b) << 16);
}
__device__ __forceinline__ void split2(float a, float b, uint32_t& hi, uint32_t& lo) {
    __nv_bfloat16 h0 = __float2bfloat16(a), h1 = __float2bfloat16(b);
    hi = pack_bf2(h0, h1);
    lo = pack_bf2(__float2bfloat16(a - __bfloat162float(h0)),
                  __float2bfloat16(b - __bfloat162float(h1)));
}

// ---------------------------------------------------------------------------
// Transpose + split W [1024,128] -> W^T [128,1024] bf16 hi/lo.
// ---------------------------------------------------------------------------
__global__ __launch_bounds__(256) void transpose_w(
    const float* __restrict__ Wq, const float* __restrict__ Wk,
    const float* __restrict__ Wv)
{
    const int w = blockIdx.y;
    const float* src = (w == 0) ? Wq : (w == 1) ? Wk : Wv;
    const int idx = blockIdx.x * 256 + threadIdx.x;   // 0..131071
    const int n = idx >> 10;
    const int k = idx & 1023;
    const float v = src[(size_t)k * HH + n];
    __nv_bfloat16 h = __float2bfloat16(v);
    g_Bhi[(size_t)w * HH * CC + idx] = h;
    g_Blo[(size_t)w * HH * CC + idx] = __float2bfloat16(v - __bfloat162float(h));
}

// ---------------------------------------------------------------------------
// HMMA projection GEMM with FUSED fp32->split-bf16 conversion of X.
// D[128,128] = A[128,1024] @ B^T, split-bf16 (3 passes). (unchanged, proven)
// ---------------------------------------------------------------------------
#define PADK       40                     // 32 k elems + 8 pad
#define TILE_BYTES (128 * PADK * 2)
#define BUF_BYTES  (4 * TILE_BYTES)
#define GEMM_SMEM  (2 * BUF_BYTES)

struct StageRegs {
    float4 xa[2], xb[2];   // 8 fp32 X values per h
    uint4  bh[2], bl[2];   // 8 bf16 Bhi/Blo per h
};

__global__ __launch_bounds__(256) void gemm_proj(const float* __restrict__ X)
{
    extern __shared__ __align__(16) char smem[];
    const uint32_t sb = smem_u32(smem);
    const int tid  = threadIdx.x;
    const int w    = tid >> 5;
    const int lane = tid & 31;
    const int mt   = blockIdx.x;
    const int wt   = blockIdx.y;

    const __nv_bfloat16* Bh = g_Bhi + (size_t)wt * HH * CC;
    const __nv_bfloat16* Bl = g_Blo + (size_t)wt * HH * CC;
    __nv_bfloat16* Oh = (wt == 0) ? g_Qhi : (wt == 1) ? g_Khi : g_Vhi;
    __nv_bfloat16* Ol = (wt == 0) ? g_Qlo : (wt == 1) ? g_Klo : g_Vlo;

    const size_t arow0 = (size_t)mt * 128;

    float acc[16][4];
    #pragma unroll
    for (int i = 0; i < 16; ++i)
        #pragma unroll
        for (int j = 0; j < 4; ++j) acc[i][j] = 0.f;

    auto ld_regs = [&](StageRegs& r, int s) {
        const int k0 = s * 32;
        #pragma unroll
        for (int h = 0; h < 2; ++h) {
            const int c   = tid + h * 256;
            const int row = c >> 2;
            const int ke  = (c & 3) * 8;
            const float* xp = X + (arow0 + row) * CC + k0 + ke;
            r.xa[h] = *(const float4*)xp;
            r.xb[h] = *(const float4*)(xp + 4);
            r.bh[h] = *(const uint4*)(Bh + (size_t)row * CC + k0 + ke);
            r.bl[h] = *(const uint4*)(Bl + (size_t)row * CC + k0 + ke);
        }
    };
    auto st_smem = [&](const StageRegs& r, int buf_i) {
        const uint32_t buf = (uint32_t)buf_i * BUF_BYTES;
        #pragma unroll
        for (int h = 0; h < 2; ++h) {
            const int c   = tid + h * 256;
            const int row = c >> 2;
            const int ke  = (c & 3) * 8;
            const uint32_t so = buf + (uint32_t)(row * PADK + ke) * 2;
            uint4 ahi, alo;
            split2(r.xa[h].x, r.xa[h].y, ahi.x, alo.x);
            split2(r.xa[h].z, r.xa[h].w, ahi.y, alo.y);
            split2(r.xb[h].x, r.xb[h].y, ahi.z, alo.z);
            split2(r.xb[h].z, r.xb[h].w, ahi.w, alo.w);
            *(uint4*)(smem + so)                  = ahi;
            *(uint4*)(smem + so + TILE_BYTES)     = alo;
            *(uint4*)(smem + so + 2 * TILE_BYTES) = r.bh[h];
            *(uint4*)(smem + so + 3 * TILE_BYTES) = r.bl[h];
        }
    };

    const int lrow  = lane & 15;
    const int lcol8 = (lane >> 4) * 8;

    {
        StageRegs r0;
        ld_regs(r0, 0);
        st_smem(r0, 0);
    }
    __syncthreads();

    for (int s = 0; s < 32; ++s) {
        StageRegs nxt;
        if (s + 1 < 32) ld_regs(nxt, s + 1);   // LDGs in flight during compute
        const uint32_t buf = sb + (uint32_t)(s & 1) * BUF_BYTES;
        #pragma unroll
        for (int kk = 0; kk < 32; kk += 16) {
            const uint32_t aaddr =
                buf + (uint32_t)((16 * w + lrow) * PADK + kk + lcol8) * 2;
            uint32_t ah[4], al[4];
            LDMX4(ah, aaddr);
            LDMX4(al, aaddr + TILE_BYTES);
            #pragma unroll
            for (int j = 0; j < 8; ++j) {
                const uint32_t baddr = buf + 2 * TILE_BYTES +
                    (uint32_t)((16 * j + lrow) * PADK + kk + lcol8) * 2;
                uint32_t bh[4], bl[4];
                LDMX4(bh, baddr);
                LDMX4(bl, baddr + TILE_BYTES);
                MMA_BF16(acc[2 * j],     ah, bh[0], bh[2]);
                MMA_BF16(acc[2 * j],     ah, bl[0], bl[2]);
                MMA_BF16(acc[2 * j],     al, bh[0], bh[2]);
                MMA_BF16(acc[2 * j + 1], ah, bh[1], bh[3]);
                MMA_BF16(acc[2 * j + 1], ah, bl[1], bl[3]);
                MMA_BF16(acc[2 * j + 1], al, bh[1], bh[3]);
            }
        }
        if (s + 1 < 32) st_smem(nxt, (s + 1) & 1);  // other buffer: safe pre-sync
        __syncthreads();
    }

    const int m0 = 16 * w + (lane >> 2);
    const int nc = (lane & 3) * 2;
    #pragma unroll
    for (int nt = 0; nt < 16; ++nt) {
        uint32_t hi, lo;
        split2(acc[nt][0], acc[nt][1], hi, lo);
        *(uint32_t*)&Oh[(arow0 + m0) * HH + nt * 8 + nc] = hi;
        *(uint32_t*)&Ol[(arow0 + m0) * HH + nt * 8 + nc] = lo;
        split2(acc[nt][2], acc[nt][3], hi, lo);
        *(uint32_t*)&Oh[(arow0 + m0 + 8) * HH + nt * 8 + nc] = hi;
        *(uint32_t*)&Ol[(arow0 + m0 + 8) * HH + nt * 8 + nc] = lo;
    }
}

// ---------------------------------------------------------------------------
// HMMA flash attention, FA2-style row ownership:
//   t-tile 128 x s-tile 64; 8 warps, each owns 16 FULL rows.
//   Softmax entirely in-warp (shuffle xor 1,2); P stays in registers
//   (S C-frag == PV A-frag). ONE barrier per iteration.
//   K tile loaded once per block; Q/V double-buffered via cp.async.
// Grid (32 t-tiles, 4 batches) = 128 CTAs; block bi does 2*bi+2 iterations.
// scores[t,s] = k[t]·q[s]/32, s <= t.
// ---------------------------------------------------------------------------
#define PADL 136
#define E_KH 0
#define E_KL 17408
#define QV0  34816                      // buffer 0 base (elems)
#define O_QH 0
#define O_QL 8704
#define O_VH 17408
#define O_VL 26112
#define QV_STRIDE 34816                 // elems per QV buffer
#define ATT_SMEM ((QV0 + 2 * QV_STRIDE) * 2)   // 208896 bytes

__global__ __launch_bounds__(256) void attn_kernel(float* __restrict__ out)
{
    extern __shared__ __align__(16) char sm[];
    const uint32_t sb = smem_u32(sm);

    const int b    = blockIdx.y;
    const int bi   = blockIdx.x;        // t-tile index (128 rows)
    const int tid  = threadIdx.x;
    const int lane = tid & 31;
    const int wid  = tid >> 5;          // 0..7: owns rows 16*wid..16*wid+15

    const size_t bo = (size_t)b * TT * HH;
    const __nv_bfloat16* Qh = g_Qhi + bo;
    const __nv_bfloat16* Ql = g_Qlo + bo;
    const __nv_bfloat16* Kh = g_Khi + bo;
    const __nv_bfloat16* Kl = g_Klo + bo;
    const __nv_bfloat16* Vh = g_Vhi + bo;
    const __nv_bfloat16* Vl = g_Vlo + bo;

    const int t0 = bi * 128;

    // async-copy a 64x128 bf16 tile (4 chunks/thread)
    auto cp64 = [&](uint32_t dstE, const __nv_bfloat16* src) {
        #pragma unroll
        for (int h = 0; h < 4; ++h) {
            const int c = tid + h * 256;            // 0..1023
            const int row = c >> 4, ch = (c & 15) * 8;
            CP_ASYNC16(sb + (uint32_t)(dstE + row * PADL + ch) * 2,
                       src + row * HH + ch);
        }
    };
    // async-copy a 128x128 bf16 tile (8 chunks/thread)
    auto cp128 = [&](uint32_t dstE, const __nv_bfloat16* src) {
        #pragma unroll
        for (int h = 0; h < 8; ++h) {
            const int c = tid + h * 256;            // 0..2047
            const int row = c >> 4, ch = (c & 15) * 8;
            CP_ASYNC16(sb + (uint32_t)(dstE + row * PADL + ch) * 2,
                       src + row * HH + ch);
        }
    };

    const int lrow  = lane & 15;
    const int lcol8 = (lane >> 4) * 8;
    const int rloc  = 16 * wid + (lane >> 2);   // local row (also rloc+8)
    const int rg0   = t0 + rloc;                // global row for r1
    const int cpair = (lane & 3) * 2;

    // K tile once + first QV tiles
    cp128(E_KH, Kh + (size_t)t0 * HH);
    cp128(E_KL, Kl + (size_t)t0 * HH);
    cp64(QV0 + O_QH, Qh);
    cp64(QV0 + O_QL, Ql);
    cp64(QV0 + O_VH, Vh);
    cp64(QV0 + O_VL, Vl);
    CP_COMMIT();

    float m0 = -1e30f, m1 = -1e30f, l0 = 0.f, l1 = 0.f;
    float accO[16][4];
    #pragma unroll
    for (int i = 0; i < 16; ++i)
        #pragma unroll
        for (int j = 0; j < 4; ++j) accO[i][j] = 0.f;

    const int jmax = 2 * bi + 1;
    for (int j = 0; j <= jmax; ++j) {
        const uint32_t buf = QV0 + (uint32_t)(j & 1) * QV_STRIDE;
        CP_WAIT0();
        __syncthreads();                 // tiles visible; all warps past PV(j-1)

        if (j < jmax) {                  // prefetch j+1 into other buffer
            const size_t s1 = (size_t)(j + 1) * 64 * HH;
            const uint32_t nb = QV0 + (uint32_t)((j + 1) & 1) * QV_STRIDE;
            cp64(nb + O_QH, Qh + s1);
            cp64(nb + O_QL, Ql + s1);
            cp64(nb + O_VH, Vh + s1);
            cp64(nb + O_VL, Vl + s1);
            CP_COMMIT();
        }

        // ---- S = K @ Q^T : rows 16*wid.., ALL 64 cols; split-bf16 ----
        float accS[8][4];
        #pragma unroll
        for (int i = 0; i < 8; ++i)
            #pragma unroll
            for (int jj = 0; jj < 4; ++jj) accS[i][jj] = 0.f;

        #pragma unroll
        for (int c8 = 0; c8 < 8; ++c8) {
            const int kk = c8 * 16;
            const uint32_t ka = sb +
                (uint32_t)((16 * wid + lrow) * PADL + kk + lcol8) * 2;
            uint32_t ah[4], al[4];
            LDMX4(ah, ka + E_KH * 2);
            LDMX4(al, ka + E_KL * 2);
            #pragma unroll
            for (int n2 = 0; n2 < 4; ++n2) {
                const uint32_t qa = sb +
                    (uint32_t)(buf + (16 * n2 + lrow) * PADL + kk + lcol8) * 2;
                uint32_t bh[4], bl[4];
                LDMX4(bh, qa + O_QH * 2);
                LDMX4(bl, qa + O_QL * 2);
                MMA_BF16(accS[2 * n2],     ah, bh[0], bh[2]);
                MMA_BF16(accS[2 * n2],     ah, bl[0], bl[2]);
                MMA_BF16(accS[2 * n2],     al, bh[0], bh[2]);
                MMA_BF16(accS[2 * n2 + 1], ah, bh[1], bh[3]);
                MMA_BF16(accS[2 * n2 + 1], ah, bl[1], bl[3]);
                MMA_BF16(accS[2 * n2 + 1], al, bh[1], bh[3]);
            }
        }

        // ---- scale + causal mask (only possible on last two tiles) ----
        if (j >= 2 * bi) {
            const int s0 = 64 * j;
            #pragma unroll
            for (int nt = 0; nt < 8; ++nt)
                #pragma unroll
                for (int e = 0; e < 2; ++e) {
                    const int cg = s0 + nt * 8 + cpair + e;
                    float v0 = accS[nt][e]     * 0.03125f;
                    float v1 = accS[nt][e + 2] * 0.03125f;
                    if (cg > rg0)     v0 = -1e30f;
                    if (cg > rg0 + 8) v1 = -1e30f;
                    accS[nt][e]     = v0;
                    accS[nt][e + 2] = v1;
                }
        } else {
            #pragma unroll
            for (int nt = 0; nt < 8; ++nt)
                #pragma unroll
                for (int e = 0; e < 4; ++e) accS[nt][e] *= 0.03125f;
        }

        // ---- in-warp row max (cols live in lanes xor 1,2 of the quad) ----
        float pm0 = -1e30f, pm1 = -1e30f;
        #pragma unroll
        for (int nt = 0; nt < 8; ++nt) {
            pm0 = fmaxf(pm0, fmaxf(accS[nt][0], accS[nt][1]));
            pm1 = fmaxf(pm1, fmaxf(accS[nt][2], accS[nt][3]));
        }
        #pragma unroll
        for (int off = 1; off <= 2; off <<= 1) {
            pm0 = fmaxf(pm0, __shfl_xor_sync(0xffffffffu, pm0, off));
            pm1 = fmaxf(pm1, __shfl_xor_sync(0xffffffffu, pm1, off));
        }
        const float mn0 = fmaxf(m0, pm0);
        const float mn1 = fmaxf(m1, pm1);

        // ---- exp + in-register P fragments + row sums ----
        float ps0 = 0.f, ps1 = 0.f;
        uint32_t pfh[4][4], pfl[4][4];   // A-frags for 4 k-chunks of 16 cols
        #pragma unroll
        for (int nt = 0; nt < 8; ++nt) {
            float p00 = __expf(accS[nt][0] - mn0);
            float p01 = __expf(accS[nt][1] - mn0);
            float p10 = __expf(accS[nt][2] - mn1);
            float p11 = __expf(accS[nt][3] - mn1);
            ps0 += p00 + p01;
            ps1 += p10 + p11;
            uint32_t hiR, loR, hiR8, loR8;
            split2(p00, p01, hiR, loR);      // row rloc   -> a0/a2
            split2(p10, p11, hiR8, loR8);    // row rloc+8 -> a1/a3
            const int c  = nt >> 1;
            const int sl = (nt & 1) * 2;
            pfh[c][sl]     = hiR;
            pfh[c][sl + 1] = hiR8;
            pfl[c][sl]     = loR;
            pfl[c][sl + 1] = loR8;
        }
        #pragma unroll
        for (int off = 1; off <= 2; off <<= 1) {
            ps0 += __shfl_xor_sync(0xffffffffu, ps0, off);
            ps1 += __shfl_xor_sync(0xffffffffu, ps1, off);
        }
        const float c0 = __expf(m0 - mn0);
        const float c1 = __expf(m1 - mn1);
        l0 = l0 * c0 + ps0;
        l1 = l1 * c1 + ps1;
        m0 = mn0;
        m1 = mn1;

        // ---- O rescale + O += P @ V (rows 16*wid.., ALL 128 h) ----
        #pragma unroll
        for (int nt = 0; nt < 16; ++nt) {
            accO[nt][0] *= c0; accO[nt][1] *= c0;
            accO[nt][2] *= c1; accO[nt][3] *= c1;
        }
        #pragma unroll
        for (int g = 0; g < 4; ++g) {        // s-chunks 16g..16g+15
            const int k2 = g * 16;
            #pragma unroll
            for (int hg = 0; hg < 8; ++hg) {     // h-groups of 16
                const uint32_t va = sb +
                    (uint32_t)(buf + (k2 + lrow) * PADL + hg * 16 + lcol8) * 2;
                uint32_t vh[4], vl[4];
                LDMX4T(vh, va + O_VH * 2);
                LDMX4T(vl, va + O_VL * 2);
                MMA_BF16(accO[2 * hg],     pfh[g], vh[0], vh[1]);
                MMA_BF16(accO[2 * hg],     pfh[g], vl[0], vl[1]);
                MMA_BF16(accO[2 * hg],     pfl[g], vh[0], vh[1]);
                MMA_BF16(accO[2 * hg + 1], pfh[g], vh[2], vh[3]);
                MMA_BF16(accO[2 * hg + 1], pfh[g], vl[2], vl[3]);
                MMA_BF16(accO[2 * hg + 1], pfl[g], vh[2], vh[3]);
            }
        }
    }

    // ---- epilogue: O / l -> out ----
    const float li0 = 1.f / l0;
    const float li1 = 1.f / l1;
    float* ob = out + ((size_t)b * TT + t0) * HH;
    #pragma unroll
    for (int nt = 0; nt < 16; ++nt) {
        const int h0 = nt * 8 + cpair;
        float2 o0 = {accO[nt][0] * li0, accO[nt][1] * li0};
        float2 o1 = {accO[nt][2] * li1, accO[nt][3] * li1};
        *(float2*)&ob[(size_t)rloc * HH + h0]       = o0;
        *(float2*)&ob[(size_t)(rloc + 8) * HH + h0] = o1;
    }
}

// ---------------------------------------------------------------------------
// Launch
// ---------------------------------------------------------------------------
extern "C" void kernel_launch(void* const* d_in, const int* in_sizes, int n_in,
                              void* d_out, int out_size)
{
    const float* ix = (const float*)d_in[0];
    const float* Wq = (const float*)d_in[1];
    const float* Wk = (const float*)d_in[2];
    const float* Wv = (const float*)d_in[3];
    float* out = (float*)d_out;

    // 1. Split weights (tiny)
    transpose_w<<<dim3((HH * CC) / 256, 3), 256>>>(Wq, Wk, Wv);

    // 2. HMMA projection GEMMs with fused fp32->split-bf16 conversion
    cudaFuncSetAttribute(gemm_proj, cudaFuncAttributeMaxDynamicSharedMemorySize,
                         GEMM_SMEM);
    gemm_proj<<<dim3(128, 3), 256, GEMM_SMEM>>>(ix);

    // 3. HMMA flash attention (FA2 row ownership, 1 barrier/iter)
    cudaFuncSetAttribute(attn_kernel, cudaFuncAttributeMaxDynamicSharedMemorySize,
                         ATT_SMEM);
    attn_kernel<<<dim3(32, 4), 256, ATT_SMEM>>>(out);
}

// round 15
// speedup vs baseline: 1.3454x; 1.3454x over previous
#include <cuda_runtime.h>
#include <cuda_bf16.h>
#include <cstdint>

// Problem constants
#define BB 4
#define TT 4096
#define CC 1024
#define HH 128

// ---------------------------------------------------------------------------
// Device scratch (no allocations allowed). Q/K/V live ONLY as split bf16.
// ---------------------------------------------------------------------------
__device__ __nv_bfloat16 g_Qhi[BB * TT * HH];
__device__ __nv_bfloat16 g_Qlo[BB * TT * HH];
__device__ __nv_bfloat16 g_Khi[BB * TT * HH];
__device__ __nv_bfloat16 g_Klo[BB * TT * HH];
__device__ __nv_bfloat16 g_Vhi[BB * TT * HH];
__device__ __nv_bfloat16 g_Vlo[BB * TT * HH];
__device__ __nv_bfloat16 g_Bhi[3 * HH * CC];        // W^T split-hi [3][128][1024]
__device__ __nv_bfloat16 g_Blo[3 * HH * CC];        // W^T split-lo

// ---------------------------------------------------------------------------
// Helpers (baseline sm_100 PTX: ldmatrix + mma.sync + cp.async)
// ---------------------------------------------------------------------------
__device__ __forceinline__ uint32_t smem_u32(const void* p) {
    uint32_t a;
    asm("{ .reg .u64 t; cvta.to.shared.u64 t, %1; cvt.u32.u64 %0, t; }"
        : "=r"(a) : "l"(p));
    return a;
}

#define LDMX4(r, addr) \
    asm volatile("ldmatrix.sync.aligned.m8n8.x4.shared.b16 {%0,%1,%2,%3}, [%4];" \
        : "=r"((r)[0]), "=r"((r)[1]), "=r"((r)[2]), "=r"((r)[3]) : "r"(addr))

#define LDMX4T(r, addr) \
    asm volatile("ldmatrix.sync.aligned.m8n8.x4.trans.shared.b16 {%0,%1,%2,%3}, [%4];" \
        : "=r"((r)[0]), "=r"((r)[1]), "=r"((r)[2]), "=r"((r)[3]) : "r"(addr))

#define MMA_BF16(c, a, b0, b1) \
    asm volatile("mma.sync.aligned.m16n8k16.row.col.f32.bf16.bf16.f32 " \
        "{%0,%1,%2,%3}, {%4,%5,%6,%7}, {%8,%9}, {%0,%1,%2,%3};" \
        : "+f"((c)[0]), "+f"((c)[1]), "+f"((c)[2]), "+f"((c)[3]) \
        : "r"((a)[0]), "r"((a)[1]), "r"((a)[2]), "r"((a)[3]), "r"(b0), "r"(b1))

#define CP_ASYNC16(saddr, gptr) \
    asm volatile("cp.async.cg.shared.global [%0], [%1], 16;" \
        :: "r"(saddr), "l"(gptr) : "memory")
#define CP_COMMIT() asm volatile("cp.async.commit_group;" ::: "memory")
#define CP_WAIT0()  asm volatile("cp.async.wait_group 0;" ::: "memory")

__device__ __forceinline__ uint32_t pack_bf2(__nv_bfloat16 a, __nv_bfloat16 b) {
    return (uint32_t)__bfloat16_as_ushort(a) |
           ((uint32_t)__bfloat16_as_ushort(b) << 16);
}
__device__ __forceinline__ void split2(float a, float b, uint32_t& hi, uint32_t& lo) {
    __nv_bfloat16 h0 = __float2bfloat16(a), h1 = __float2bfloat16(b);
    hi = pack_bf2(h0, h1);
    lo = pack_bf2(__float2bfloat16(a - __bfloat162float(h0)),
                  __float2bfloat16(b - __bfloat162float(h1)));
}

// ---------------------------------------------------------------------------
// Transpose + split W [1024,128] -> W^T [128,1024] bf16 hi/lo.
// ---------------------------------------------------------------------------
__global__ __launch_bounds__(256) void transpose_w(
    const float* __restrict__ Wq, const float* __restrict__ Wk,
    const float* __restrict__ Wv)
{
    const int w = blockIdx.y;
    const float* src = (w == 0) ? Wq : (w == 1) ? Wk : Wv;
    const int idx = blockIdx.x * 256 + threadIdx.x;   // 0..131071
    const int n = idx >> 10;
    const int k = idx & 1023;
    const float v = src[(size_t)k * HH + n];
    __nv_bfloat16 h = __float2bfloat16(v);
    g_Bhi[(size_t)w * HH * CC + idx] = h;
    g_Blo[(size_t)w * HH * CC + idx] = __float2bfloat16(v - __bfloat162float(h));
}

// ---------------------------------------------------------------------------
// HMMA projection GEMM with FUSED fp32->split-bf16 conversion of X.
// D[128,128] = A[128,1024] @ B^T, split-bf16 (3 passes). (unchanged, proven)
// ---------------------------------------------------------------------------
#define PADK       40                     // 32 k elems + 8 pad
#define TILE_BYTES (128 * PADK * 2)
#define BUF_BYTES  (4 * TILE_BYTES)
#define GEMM_SMEM  (2 * BUF_BYTES)

struct StageRegs {
    float4 xa[2], xb[2];   // 8 fp32 X values per h
    uint4  bh[2], bl[2];   // 8 bf16 Bhi/Blo per h
};

__global__ __launch_bounds__(256) void gemm_proj(const float* __restrict__ X)
{
    extern __shared__ __align__(16) char smem[];
    const uint32_t sb = smem_u32(smem);
    const int tid  = threadIdx.x;
    const int w    = tid >> 5;
    const int lane = tid & 31;
    const int mt   = blockIdx.x;
    const int wt   = blockIdx.y;

    const __nv_bfloat16* Bh = g_Bhi + (size_t)wt * HH * CC;
    const __nv_bfloat16* Bl = g_Blo + (size_t)wt * HH * CC;
    __nv_bfloat16* Oh = (wt == 0) ? g_Qhi : (wt == 1) ? g_Khi : g_Vhi;
    __nv_bfloat16* Ol = (wt == 0) ? g_Qlo : (wt == 1) ? g_Klo : g_Vlo;

    const size_t arow0 = (size_t)mt * 128;

    float acc[16][4];
    #pragma unroll
    for (int i = 0; i < 16; ++i)
        #pragma unroll
        for (int j = 0; j < 4; ++j) acc[i][j] = 0.f;

    auto ld_regs = [&](StageRegs& r, int s) {
        const int k0 = s * 32;
        #pragma unroll
        for (int h = 0; h < 2; ++h) {
            const int c   = tid + h * 256;
            const int row = c >> 2;
            const int ke  = (c & 3) * 8;
            const float* xp = X + (arow0 + row) * CC + k0 + ke;
            r.xa[h] = *(const float4*)xp;
            r.xb[h] = *(const float4*)(xp + 4);
            r.bh[h] = *(const uint4*)(Bh + (size_t)row * CC + k0 + ke);
            r.bl[h] = *(const uint4*)(Bl + (size_t)row * CC + k0 + ke);
        }
    };
    auto st_smem = [&](const StageRegs& r, int buf_i) {
        const uint32_t buf = (uint32_t)buf_i * BUF_BYTES;
        #pragma unroll
        for (int h = 0; h < 2; ++h) {
            const int c   = tid + h * 256;
            const int row = c >> 2;
            const int ke  = (c & 3) * 8;
            const uint32_t so = buf + (uint32_t)(row * PADK + ke) * 2;
            uint4 ahi, alo;
            split2(r.xa[h].x, r.xa[h].y, ahi.x, alo.x);
            split2(r.xa[h].z, r.xa[h].w, ahi.y, alo.y);
            split2(r.xb[h].x, r.xb[h].y, ahi.z, alo.z);
            split2(r.xb[h].z, r.xb[h].w, ahi.w, alo.w);
            *(uint4*)(smem + so)                  = ahi;
            *(uint4*)(smem + so + TILE_BYTES)     = alo;
            *(uint4*)(smem + so + 2 * TILE_BYTES) = r.bh[h];
            *(uint4*)(smem + so + 3 * TILE_BYTES) = r.bl[h];
        }
    };

    const int lrow  = lane & 15;
    const int lcol8 = (lane >> 4) * 8;

    {
        StageRegs r0;
        ld_regs(r0, 0);
        st_smem(r0, 0);
    }
    __syncthreads();

    for (int s = 0; s < 32; ++s) {
        StageRegs nxt;
        if (s + 1 < 32) ld_regs(nxt, s + 1);   // LDGs in flight during compute
        const uint32_t buf = sb + (uint32_t)(s & 1) * BUF_BYTES;
        #pragma unroll
        for (int kk = 0; kk < 32; kk += 16) {
            const uint32_t aaddr =
                buf + (uint32_t)((16 * w + lrow) * PADK + kk + lcol8) * 2;
            uint32_t ah[4], al[4];
            LDMX4(ah, aaddr);
            LDMX4(al, aaddr + TILE_BYTES);
            #pragma unroll
            for (int j = 0; j < 8; ++j) {
                const uint32_t baddr = buf + 2 * TILE_BYTES +
                    (uint32_t)((16 * j + lrow) * PADK + kk + lcol8) * 2;
                uint32_t bh[4], bl[4];
                LDMX4(bh, baddr);
                LDMX4(bl, baddr + TILE_BYTES);
                MMA_BF16(acc[2 * j],     ah, bh[0], bh[2]);
                MMA_BF16(acc[2 * j],     ah, bl[0], bl[2]);
                MMA_BF16(acc[2 * j],     al, bh[0], bh[2]);
                MMA_BF16(acc[2 * j + 1], ah, bh[1], bh[3]);
                MMA_BF16(acc[2 * j + 1], ah, bl[1], bl[3]);
                MMA_BF16(acc[2 * j + 1], al, bh[1], bh[3]);
            }
        }
        if (s + 1 < 32) st_smem(nxt, (s + 1) & 1);  // other buffer: safe pre-sync
        __syncthreads();
    }

    const int m0 = 16 * w + (lane >> 2);
    const int nc = (lane & 3) * 2;
    #pragma unroll
    for (int nt = 0; nt < 16; ++nt) {
        uint32_t hi, lo;
        split2(acc[nt][0], acc[nt][1], hi, lo);
        *(uint32_t*)&Oh[(arow0 + m0) * HH + nt * 8 + nc] = hi;
        *(uint32_t*)&Ol[(arow0 + m0) * HH + nt * 8 + nc] = lo;
        split2(acc[nt][2], acc[nt][3], hi, lo);
        *(uint32_t*)&Oh[(arow0 + m0 + 8) * HH + nt * 8 + nc] = hi;
        *(uint32_t*)&Ol[(arow0 + m0 + 8) * HH + nt * 8 + nc] = lo;
    }
}

// ---------------------------------------------------------------------------
// HMMA flash attention: round-9 balanced structure with interleaved
// (pass-major) MMA issue order. asm volatile fixes SASS order, so source
// interleaving is the only way to break h.h->h.l->l.h dependent chains;
// 4 independent accumulators sit between dependent reuses.
// Per-accumulator operand order unchanged -> bitwise-identical numerics.
// scores[t,s] = k[t]·q[s]/32, s <= t. 256 thr / 8 warps, 64x64 tiles, D=128.
// cp.async double-buffered Q/V; 3 barriers/iter; m/l in registers.
// Pairing: block p does t-tiles {63-p, p} -> 65 s-tiles each; grid (32,4).
// ---------------------------------------------------------------------------
#define PADL 136
#define PADP 72
#define E_KH 0
#define E_KL 8704
#define E_QH0 17408
#define E_QL0 26112
#define E_VH0 34816
#define E_VL0 43520
#define BUF_STRIDE 34816               // elems between QV buffer 0 and 1
#define E_PH 87040
#define E_PL 91648
#define RED_BYTE 192512                // 96256 elems * 2
#define ATT_SMEM (RED_BYTE + 256 * 4)

__global__ __launch_bounds__(256) void attn_kernel(float* __restrict__ out)
{
    extern __shared__ __align__(16) char sm[];
    float* rmax2 = (float*)(sm + RED_BYTE);   // [64][2]
    float* rsum2 = rmax2 + 128;               // [64][2]
    const uint32_t sb = smem_u32(sm);

    const int b    = blockIdx.y;
    const int pair = blockIdx.x;
    const int tid  = threadIdx.x;
    const int lane = tid & 31;
    const int wid  = tid >> 5;
    const int wr   = wid & 3;           // row group: rows 16*wr..16*wr+15
    const int wc   = wid >> 2;          // col/h group: 0..1

    const size_t bo = (size_t)b * TT * HH;
    const __nv_bfloat16* Qh = g_Qhi + bo;
    const __nv_bfloat16* Ql = g_Qlo + bo;
    const __nv_bfloat16* Kh = g_Khi + bo;
    const __nv_bfloat16* Kl = g_Klo + bo;
    const __nv_bfloat16* Vh = g_Vhi + bo;
    const __nv_bfloat16* Vl = g_Vlo + bo;

    const int lrow  = lane & 15;
    const int lcol8 = (lane >> 4) * 8;
    const int r1    = 16 * wr + (lane >> 2);   // local row (0..63); also r1+8
    const int cpair = (lane & 3) * 2;

    // async-copy one 64x128 bf16 tile into smem (stride PADL)
    auto cp_tile = [&](uint32_t dstE, const __nv_bfloat16* src) {
        #pragma unroll
        for (int h = 0; h < 4; ++h) {
            const int c = tid + h * 256;            // 0..1023
            const int row = c >> 4, ch = (c & 15) * 8;
            CP_ASYNC16(sb + (uint32_t)(dstE + row * PADL + ch) * 2,
                       src + row * HH + ch);
        }
    };

    for (int half = 0; half < 2; ++half) {
        const int it = (half == 0) ? (63 - pair) : pair;
        const int t0 = it * 64;

        __syncthreads();                 // prior half fully done with smem
        cp_tile(E_KH, Kh + (size_t)t0 * HH);
        cp_tile(E_KL, Kl + (size_t)t0 * HH);
        cp_tile(E_QH0, Qh);              // j=0 tile (s0 = 0)
        cp_tile(E_QL0, Ql);
        cp_tile(E_VH0, Vh);
        cp_tile(E_VL0, Vl);
        CP_COMMIT();

        float m0 = -1e30f, m1 = -1e30f, l0 = 0.f, l1 = 0.f;
        float accO[8][4];
        #pragma unroll
        for (int i = 0; i < 8; ++i)
            #pragma unroll
            for (int j = 0; j < 4; ++j) accO[i][j] = 0.f;

        for (int j = 0; j <= it; ++j) {
            const uint32_t buf = (uint32_t)(j & 1) * BUF_STRIDE;
            CP_WAIT0();
            __syncthreads();             // tiles visible; all warps past PV(j-1)

            if (j < it) {                // prefetch j+1 into other buffer
                const size_t s1 = (size_t)(j + 1) * 64 * HH;
                const uint32_t nb = (uint32_t)((j + 1) & 1) * BUF_STRIDE;
                cp_tile(E_QH0 + nb, Qh + s1);
                cp_tile(E_QL0 + nb, Ql + s1);
                cp_tile(E_VH0 + nb, Vh + s1);
                cp_tile(E_VL0 + nb, Vl + s1);
                CP_COMMIT();
            }

            // ---- S = K @ Q^T (rows 16*wr.., cols 32*wc..), split-bf16 ----
            float sA0[4] = {0.f, 0.f, 0.f, 0.f};
            float sA1[4] = {0.f, 0.f, 0.f, 0.f};
            float sA2[4] = {0.f, 0.f, 0.f, 0.f};
            float sA3[4] = {0.f, 0.f, 0.f, 0.f};

            #pragma unroll
            for (int kk = 0; kk < 128; kk += 16) {
                const uint32_t ka = sb +
                    (uint32_t)((16 * wr + lrow) * PADL + kk + lcol8) * 2;
                const uint32_t qa0 = sb +
                    (uint32_t)(buf + (32 * wc + lrow) * PADL + kk + lcol8) * 2;
                const uint32_t qa1 = qa0 + (uint32_t)(16 * PADL) * 2;
                uint32_t ah[4], al[4], q0h[4], q0l[4], q1h[4], q1l[4];
                LDMX4(ah, ka + E_KH * 2);
                LDMX4(al, ka + E_KL * 2);
                LDMX4(q0h, qa0 + E_QH0 * 2);
                LDMX4(q0l, qa0 + E_QL0 * 2);
                LDMX4(q1h, qa1 + E_QH0 * 2);
                LDMX4(q1l, qa1 + E_QL0 * 2);
                // interleaved issue: 4 independent targets between reuses
                MMA_BF16(sA0, ah, q0h[0], q0h[2]);
                MMA_BF16(sA1, ah, q0h[1], q0h[3]);
                MMA_BF16(sA2, ah, q1h[0], q1h[2]);
                MMA_BF16(sA3, ah, q1h[1], q1h[3]);
                MMA_BF16(sA0, ah, q0l[0], q0l[2]);
                MMA_BF16(sA1, ah, q0l[1], q0l[3]);
                MMA_BF16(sA2, ah, q1l[0], q1l[2]);
                MMA_BF16(sA3, ah, q1l[1], q1l[3]);
                MMA_BF16(sA0, al, q0h[0], q0h[2]);
                MMA_BF16(sA1, al, q0h[1], q0h[3]);
                MMA_BF16(sA2, al, q1h[0], q1h[2]);
                MMA_BF16(sA3, al, q1h[1], q1h[3]);
            }

            float accS[4][4];
            #pragma unroll
            for (int e = 0; e < 4; ++e) {
                accS[0][e] = sA0[e];
                accS[1][e] = sA1[e];
                accS[2][e] = sA2[e];
                accS[3][e] = sA3[e];
            }

            // ---- scale + causal mask ----
            const bool diag = (j == it);
            #pragma unroll
            for (int nt = 0; nt < 4; ++nt)
                #pragma unroll
                for (int e = 0; e < 2; ++e) {
                    const int col = 32 * wc + nt * 8 + cpair + e;
                    float v0 = accS[nt][e]     * 0.03125f;
                    float v1 = accS[nt][e + 2] * 0.03125f;
                    if (diag && col > r1)     v0 = -1e30f;
                    if (diag && col > r1 + 8) v1 = -1e30f;
                    accS[nt][e]     = v0;
                    accS[nt][e + 2] = v1;
                }

            // ---- partial row max (this warp's 32 cols) ----
            float pm0 = -1e30f, pm1 = -1e30f;
            #pragma unroll
            for (int nt = 0; nt < 4; ++nt) {
                pm0 = fmaxf(pm0, fmaxf(accS[nt][0], accS[nt][1]));
                pm1 = fmaxf(pm1, fmaxf(accS[nt][2], accS[nt][3]));
            }
            #pragma unroll
            for (int off = 1; off <= 2; off <<= 1) {
                pm0 = fmaxf(pm0, __shfl_xor_sync(0xffffffffu, pm0, off));
                pm1 = fmaxf(pm1, __shfl_xor_sync(0xffffffffu, pm1, off));
            }
            if ((lane & 3) == 0) {
                rmax2[r1 * 2 + wc]       = pm0;
                rmax2[(r1 + 8) * 2 + wc] = pm1;
            }
            __syncthreads();

            // ---- exp + partial sums + store P (bf16 hi/lo) ----
            const float mn0 = fmaxf(m0, fmaxf(rmax2[r1 * 2], rmax2[r1 * 2 + 1]));
            const float mn1 = fmaxf(m1, fmaxf(rmax2[(r1 + 8) * 2], rmax2[(r1 + 8) * 2 + 1]));
            float ps0 = 0.f, ps1 = 0.f;
            #pragma unroll
            for (int nt = 0; nt < 4; ++nt) {
                float p00 = __expf(accS[nt][0] - mn0);
                float p01 = __expf(accS[nt][1] - mn0);
                float p10 = __expf(accS[nt][2] - mn1);
                float p11 = __expf(accS[nt][3] - mn1);
                ps0 += p00 + p01;
                ps1 += p10 + p11;
                uint32_t hi, lo;
                const int col = 32 * wc + nt * 8 + cpair;
                split2(p00, p01, hi, lo);
                *(uint32_t*)(sm + (uint32_t)(E_PH + r1 * PADP + col) * 2) = hi;
                *(uint32_t*)(sm + (uint32_t)(E_PL + r1 * PADP + col) * 2) = lo;
                split2(p10, p11, hi, lo);
                *(uint32_t*)(sm + (uint32_t)(E_PH + (r1 + 8) * PADP + col) * 2) = hi;
                *(uint32_t*)(sm + (uint32_t)(E_PL + (r1 + 8) * PADP + col) * 2) = lo;
            }
            #pragma unroll
            for (int off = 1; off <= 2; off <<= 1) {
                ps0 += __shfl_xor_sync(0xffffffffu, ps0, off);
                ps1 += __shfl_xor_sync(0xffffffffu, ps1, off);
            }
            if ((lane & 3) == 0) {
                rsum2[r1 * 2 + wc]       = ps0;
                rsum2[(r1 + 8) * 2 + wc] = ps1;
            }
            __syncthreads();

            // ---- register m/l update (redundant across row owners) ----
            const float c0 = __expf(m0 - mn0);
            const float c1 = __expf(m1 - mn1);
            l0 = l0 * c0 + rsum2[r1 * 2] + rsum2[r1 * 2 + 1];
            l1 = l1 * c1 + rsum2[(r1 + 8) * 2] + rsum2[(r1 + 8) * 2 + 1];
            m0 = mn0;
            m1 = mn1;

            // ---- O rescale + O += P @ V (warp: rows 16*wr.., h 64*wc..) ----
            #pragma unroll
            for (int nt = 0; nt < 8; ++nt) {
                accO[nt][0] *= c0; accO[nt][1] *= c0;
                accO[nt][2] *= c1; accO[nt][3] *= c1;
            }
            #pragma unroll
            for (int k2 = 0; k2 < 64; k2 += 16) {
                const uint32_t pa = sb +
                    (uint32_t)((16 * wr + lrow) * PADP + k2 + lcol8) * 2;
                uint32_t ph[4], pl[4];
                LDMX4(ph, pa + E_PH * 2);
                LDMX4(pl, pa + E_PL * 2);
                #pragma unroll
                for (int n4p = 0; n4p < 4; n4p += 2) {
                    const uint32_t va0 = sb +
                        (uint32_t)(buf + (k2 + lrow) * PADL + 64 * wc + n4p * 16 + lcol8) * 2;
                    const uint32_t va1 = va0 + 16 * 2;
                    uint32_t v0h[4], v0l[4], v1h[4], v1l[4];
                    LDMX4T(v0h, va0 + E_VH0 * 2);
                    LDMX4T(v0l, va0 + E_VL0 * 2);
                    LDMX4T(v1h, va1 + E_VH0 * 2);
                    LDMX4T(v1l, va1 + E_VL0 * 2);
                    // interleaved issue: 4 independent targets between reuses
                    MMA_BF16(accO[2 * n4p],     ph, v0h[0], v0h[1]);
                    MMA_BF16(accO[2 * n4p + 1], ph, v0h[2], v0h[3]);
                    MMA_BF16(accO[2 * n4p + 2], ph, v1h[0], v1h[1]);
                    MMA_BF16(accO[2 * n4p + 3], ph, v1h[2], v1h[3]);
                    MMA_BF16(accO[2 * n4p],     ph, v0l[0], v0l[1]);
                    MMA_BF16(accO[2 * n4p + 1], ph, v0l[2], v0l[3]);
                    MMA_BF16(accO[2 * n4p + 2], ph, v1l[0], v1l[1]);
                    MMA_BF16(accO[2 * n4p + 3], ph, v1l[2], v1l[3]);
                    MMA_BF16(accO[2 * n4p],     pl, v0h[0], v0h[1]);
                    MMA_BF16(accO[2 * n4p + 1], pl, v0h[2], v0h[3]);
                    MMA_BF16(accO[2 * n4p + 2], pl, v1h[0], v1h[1]);
                    MMA_BF16(accO[2 * n4p + 3], pl, v1h[2], v1h[3]);
                }
            }
        }

        // ---- epilogue: O / l -> out ----
        const float li0 = 1.f / l0;
        const float li1 = 1.f / l1;
        float* ob = out + ((size_t)b * TT + t0) * HH;
        #pragma unroll
        for (int nt = 0; nt < 8; ++nt) {
            const int h0 = 64 * wc + nt * 8 + cpair;
            float2 o0 = {accO[nt][0] * li0, accO[nt][1] * li0};
            float2 o1 = {accO[nt][2] * li1, accO[nt][3] * li1};
            *(float2*)&ob[(size_t)r1 * HH + h0]       = o0;
            *(float2*)&ob[(size_t)(r1 + 8) * HH + h0] = o1;
        }
    }
}

// ---------------------------------------------------------------------------
// Launch
// ---------------------------------------------------------------------------
extern "C" void kernel_launch(void* const* d_in, const int* in_sizes, int n_in,
                              void* d_out, int out_size)
{
    const float* ix = (const float*)d_in[0];
    const float* Wq = (const float*)d_in[1];
    const float* Wk = (const float*)d_in[2];
    const float* Wv = (const float*)d_in[3];
    float* out = (float*)d_out;

    // 1. Split weights (tiny)
    transpose_w<<<dim3((HH * CC) / 256, 3), 256>>>(Wq, Wk, Wv);

    // 2. HMMA projection GEMMs with fused fp32->split-bf16 conversion
    cudaFuncSetAttribute(gemm_proj, cudaFuncAttributeMaxDynamicSharedMemorySize,
                         GEMM_SMEM);
    gemm_proj<<<dim3(128, 3), 256, GEMM_SMEM>>>(ix);

    // 3. HMMA flash attention (interleaved/pass-major MMA issue order)
    cudaFuncSetAttribute(attn_kernel, cudaFuncAttributeMaxDynamicSharedMemorySize,
                         ATT_SMEM);
    attn_kernel<<<dim3(32, 4), 256, ATT_SMEM>>>(out);
}